// round 3
// baseline (speedup 1.0000x reference)
#include <cuda_runtime.h>
#include <cuda_bf16.h>

#define BS 16
#define NQ 300
#define NT 50
#define KP3 51          // 17 keypoints * 3
#define NCOL (BS*NT)    // 800
#define NROW (BS*NQ)    // 4800
#define NK 10           // columns per lane in LAP (10*32 >= 300)
#define CBLK 160        // cols per cost block
#define RBLK 96         // rows per cost block

__device__ float g_lap[BS*NT*NQ];      // per-batch transposed cost [b][t][q]

// monotonic float<->uint order-preserving map (for redux.min)
__device__ __forceinline__ unsigned fmap(float f) {
    unsigned u = __float_as_uint(f);
    return (u & 0x80000000u) ? ~u : (u | 0x80000000u);
}
__device__ __forceinline__ float finv(unsigned u) {
    return __uint_as_float((u & 0x80000000u) ? (u & 0x7FFFFFFFu) : ~u);
}

// ---------------------------------------------------------
// Kernel 1: cost matrix, fused target preprocessing.
// block = 160 threads (one column each), 96 rows per block.
// grid = (800/160, 4800/96) = (5, 50)
// ---------------------------------------------------------
__global__ void __launch_bounds__(CBLK) cost_kernel(const float* __restrict__ pkp,
                                                    const float* __restrict__ pbox,
                                                    const float* __restrict__ tkp,
                                                    const float* __restrict__ tbox,
                                                    float* __restrict__ C) {
    __shared__ float buf[CBLK*KP3 + CBLK*6];   // phase A: tgt slice; phase B: pred slice
    const int tid = threadIdx.x;
    const int c0  = blockIdx.x * CBLK;
    const int r0  = blockIdx.y * RBLK;
    const int c   = c0 + tid;

    // ---- phase A: coalesced load of target slice, then to registers ----
    for (int i = tid; i < CBLK*KP3; i += CBLK) buf[i] = tkp[c0*KP3 + i];
    for (int i = tid; i < CBLK*6;  i += CBLK) buf[CBLK*KP3 + i] = tbox[c0*6 + i];
    __syncthreads();

    float dk[KP3], tmn[3], tmx[3], tvol;
    {
        float sz[3];
        #pragma unroll
        for (int d = 0; d < 3; d++) {
            float ctr = buf[CBLK*KP3 + tid*6 + d];
            sz[d]     = buf[CBLK*KP3 + tid*6 + 3 + d];
            tmn[d] = ctr - 0.5f*sz[d];
            tmx[d] = ctr + 0.5f*sz[d];
        }
        tvol = (tmx[0]-tmn[0])*(tmx[1]-tmn[1])*(tmx[2]-tmn[2]);
        #pragma unroll
        for (int k = 0; k < KP3; k++) {
            int d = k - (k/3)*3;
            dk[k] = (buf[tid*KP3 + k] - tmn[d]) / sz[d];
        }
    }
    __syncthreads();

    // ---- phase B: coalesced load of pred row slice ----
    for (int i = tid; i < RBLK*KP3; i += CBLK) buf[i] = pkp[(size_t)r0*KP3 + i];
    for (int i = tid; i < RBLK*6;  i += CBLK) buf[RBLK*KP3 + i] = pbox[(size_t)r0*6 + i];
    __syncthreads();

    const int bc   = c / NT;        // batch owning this target column
    const int tloc = c - bc*NT;

    for (int r = 0; r < RBLK; r++) {
        // keypoint L1 cost: broadcast LDS + 2 FADD per element
        float s = 0.f;
        #pragma unroll
        for (int k = 0; k < KP3; k++) s += fabsf(buf[r*KP3 + k] - dk[k]);

        // GIoU
        float pmn[3], pmx[3];
        #pragma unroll
        for (int d = 0; d < 3; d++) {
            float cc = buf[RBLK*KP3 + r*6 + d];
            float ss = buf[RBLK*KP3 + r*6 + 3 + d];
            pmn[d] = cc - 0.5f*ss; pmx[d] = cc + 0.5f*ss;
        }
        float vol1 = (pmx[0]-pmn[0])*(pmx[1]-pmn[1])*(pmx[2]-pmn[2]);
        float inter = 1.f, evol = 1.f;
        #pragma unroll
        for (int d = 0; d < 3; d++) {
            inter *= fmaxf(fminf(pmx[d], tmx[d]) - fmaxf(pmn[d], tmn[d]), 0.f);
            evol  *= fmaxf(fmaxf(pmx[d], tmx[d]) - fminf(pmn[d], tmn[d]), 0.f);
        }
        float uni  = vol1 + tvol - inter;
        float cost = s - (inter/uni - (evol - uni)/evol);

        int rr = r0 + r;
        C[(size_t)rr*NCOL + c] = cost;
        if (rr / NQ == bc)                        // diagonal block -> LAP staging
            g_lap[(size_t)(bc*NT + tloc)*NQ + (rr - bc*NQ)] = cost;
    }
}

// ---------------------------------------------------------
// Kernel 2: LAP. 16 blocks x 256 threads; 256 threads stage the 50x300
// cost block into dynamic smem (float4), warp 0 solves with register
// shortest/v and redux.sync argmin.
// ---------------------------------------------------------
__global__ void __launch_bounds__(256) lap_kernel(float* __restrict__ out) {
    extern __shared__ float smc[];         // [NT*NQ] cost block
    const int b   = blockIdx.x;
    const int tid = threadIdx.x;

    // cooperative coalesced load of the batch cost block
    {
        const float4* src = (const float4*)&g_lap[(size_t)b*NT*NQ];
        float4* dst = (float4*)smc;
        #pragma unroll 4
        for (int i = tid; i < NT*NQ/4; i += 256) dst[i] = src[i];
    }
    __syncthreads();
    if (tid >= 32) return;                 // warp 0 solves alone

    const int lane = tid;
    const float INF = 3.0e38f;

    __shared__ float u[NT];
    __shared__ int   path[NQ];
    __shared__ int   row4col[NQ];
    __shared__ int   col4row[NT];
    __shared__ int   selj[NQ + 2];
    __shared__ float selv[NQ + 2];

    float shortest[NK];
    float vloc[NK];

    for (int j = lane; j < NQ; j += 32) row4col[j] = -1;
    for (int t = lane; t < NT; t += 32) { u[t] = 0.f; col4row[t] = -1; }
    #pragma unroll
    for (int k = 0; k < NK; k++) vloc[k] = 0.f;
    __syncwarp();

    for (int curRow = 0; curRow < NT; curRow++) {
        #pragma unroll
        for (int k = 0; k < NK; k++) shortest[k] = INF;
        unsigned sc = 0;
        int   i  = curRow;
        float mv = 0.f;
        int   nsteps = 0;
        int   sink = -1;

        while (true) {
            const float base = mv - u[i];
            const float* lrow = smc + i*NQ;

            float bv = INF; int bi = NQ;
            #pragma unroll
            for (int k = 0; k < NK; k++) {
                int j = k*32 + lane;
                if (j < NQ && !((sc >> k) & 1u)) {
                    float rr = base + lrow[j] - vloc[k];
                    if (rr < shortest[k]) { shortest[k] = rr; path[j] = i; }
                    if (shortest[k] < bv) { bv = shortest[k]; bi = j; }
                }
            }

            // warp argmin via redux: min value, then min index among ties
            unsigned bu  = fmap(bv);
            unsigned mvu = __reduce_min_sync(0xffffffffu, bu);
            unsigned cand = (bu == mvu) ? (unsigned)bi : 0x7fffffffu;
            int fi = (int)__reduce_min_sync(0xffffffffu, cand);
            mv = finv(mvu);

            if (lane == (fi & 31)) sc |= 1u << (fi >> 5);
            if (lane == 0) { selj[nsteps] = fi; selv[nsteps] = mv; }
            nsteps++;

            int r4 = row4col[fi];
            if (r4 == -1) { sink = fi; break; }
            i = r4;
        }

        __syncwarp();

        // dual updates (pre-augmentation row4col)
        if (lane == 0) u[curRow] += mv;
        for (int s = lane; s < nsteps - 1; s += 32) {
            int i2 = row4col[selj[s]];
            u[i2] += mv - selv[s];
        }
        for (int s = 0; s < nsteps; s++) {
            int j = selj[s];
            if ((j & 31) == lane) vloc[j >> 5] -= mv - selv[s];
        }
        __syncwarp();

        // augment
        if (lane == 0) {
            int j = sink;
            while (true) {
                int i2 = path[j];
                row4col[j] = i2;
                int nj = col4row[i2];
                col4row[i2] = j;
                j = nj;
                if (i2 == curRow) break;
            }
        }
        __syncwarp();
    }

    // emit indices sorted by query (rank counting)
    for (int t = lane; t < NT; t += 32) {
        int q = col4row[t];
        int rank = 0;
        #pragma unroll
        for (int t2 = 0; t2 < NT; t2++) rank += (col4row[t2] < q) ? 1 : 0;
        size_t base = (size_t)NROW * NCOL + (size_t)b * 2 * NT;
        out[base + rank]      = (float)q;
        out[base + NT + rank] = (float)t;
    }
}

// ---------------------------------------------------------
extern "C" void kernel_launch(void* const* d_in, const int* in_sizes, int n_in,
                              void* d_out, int out_size) {
    const float* pred_kp   = (const float*)d_in[0];  // (16,300,51)
    const float* pred_box  = (const float*)d_in[1];  // (16,300,6)
    const float* tgt_box   = (const float*)d_in[2];  // (16,50,6)
    const float* tgt_kp    = (const float*)d_in[3];  // (16,50,51)
    float* out = (float*)d_out;

    static_assert(NT*NQ % 4 == 0, "float4 load");
    const int lap_smem = NT*NQ*(int)sizeof(float);   // 60000 B > 48KB static limit
    cudaFuncSetAttribute(lap_kernel, cudaFuncAttributeMaxDynamicSharedMemorySize, lap_smem);

    dim3 cg(NCOL/CBLK, NROW/RBLK);     // (5, 50)
    cost_kernel<<<cg, CBLK>>>(pred_kp, pred_box, tgt_kp, tgt_box, out);

    lap_kernel<<<BS, 256, lap_smem>>>(out);
}

// round 4
// speedup vs baseline: 1.4670x; 1.4670x over previous
#include <cuda_runtime.h>
#include <cuda_bf16.h>

#define BS 16
#define NQ 300
#define NT 50
#define KP3 51          // 17 keypoints * 3
#define KPP 52          // padded (float4-friendly)
#define NCOL (BS*NT)    // 800
#define NROW (BS*NQ)    // 4800
#define NK 10           // columns per lane in LAP (10*32 >= 300)
#define CBLK 160        // cols per cost block
#define RBLK 96         // rows per cost block

__device__ float g_lap[BS*NT*NQ];      // per-batch transposed cost [b][t][q]

// monotonic float<->uint order-preserving map (for redux.min)
__device__ __forceinline__ unsigned fmap(float f) {
    unsigned u = __float_as_uint(f);
    return (u & 0x80000000u) ? ~u : (u | 0x80000000u);
}
__device__ __forceinline__ float finv(unsigned u) {
    return __uint_as_float((u & 0x80000000u) ? (u & 0x7FFFFFFFu) : ~u);
}

// warp argmin with lowest-index tie-break; returns (val via ref, idx)
__device__ __forceinline__ int warp_argmin(float& bv, int bi) {
    unsigned bu  = fmap(bv);
    unsigned mvu = __reduce_min_sync(0xffffffffu, bu);
    unsigned cand = (bu == mvu) ? (unsigned)bi : 0x7fffffffu;
    int fi = (int)__reduce_min_sync(0xffffffffu, cand);
    bv = finv(mvu);
    return fi;
}

// ---------------------------------------------------------
// Kernel 1: cost matrix, fused target preprocessing.
// block = 160 threads (one column each), 96 rows per block. grid (5,50).
// ---------------------------------------------------------
__global__ void __launch_bounds__(CBLK) cost_kernel(const float* __restrict__ pkp,
                                                    const float* __restrict__ pbox,
                                                    const float* __restrict__ tkp,
                                                    const float* __restrict__ tbox,
                                                    float* __restrict__ C) {
    __shared__ __align__(16) float buf[CBLK*(KP3+6)];   // A: tgt slice; B: pred slice
    const int tid = threadIdx.x;
    const int c0  = blockIdx.x * CBLK;
    const int r0  = blockIdx.y * RBLK;
    const int c   = c0 + tid;

    // ---- phase A: coalesced load of target slice, then to registers ----
    for (int i = tid; i < CBLK*KP3; i += CBLK) buf[i] = tkp[c0*KP3 + i];
    for (int i = tid; i < CBLK*6;  i += CBLK) buf[CBLK*KP3 + i] = tbox[c0*6 + i];
    __syncthreads();

    float dk[KPP], tmn[3], tmx[3], tvol;
    {
        float sz[3];
        #pragma unroll
        for (int d = 0; d < 3; d++) {
            float ctr = buf[CBLK*KP3 + tid*6 + d];
            sz[d]     = buf[CBLK*KP3 + tid*6 + 3 + d];
            tmn[d] = ctr - 0.5f*sz[d];
            tmx[d] = ctr + 0.5f*sz[d];
        }
        tvol = (tmx[0]-tmn[0])*(tmx[1]-tmn[1])*(tmx[2]-tmn[2]);
        #pragma unroll
        for (int k = 0; k < KP3; k++) {
            int d = k - (k/3)*3;
            dk[k] = (buf[tid*KP3 + k] - tmn[d]) / sz[d];
        }
        dk[KP3] = 0.f;   // pad
    }
    __syncthreads();

    // ---- phase B: pred rows padded to 52 floats + boxes ----
    for (int i = tid; i < RBLK*KPP; i += CBLK) {
        int r = i / KPP, k = i - r*KPP;
        buf[i] = (k < KP3) ? pkp[(size_t)(r0+r)*KP3 + k] : 0.f;
    }
    for (int i = tid; i < RBLK*6;  i += CBLK) buf[RBLK*KPP + i] = pbox[(size_t)r0*6 + i];
    __syncthreads();

    const int bc   = c / NT;        // batch owning this target column
    const int tloc = c - bc*NT;

    for (int r = 0; r < RBLK; r++) {
        // keypoint L1 cost: 13 x LDS.128 + ILP accumulators
        const float4* prow = (const float4*)&buf[r*KPP];
        float s0 = 0.f, s1 = 0.f, s2 = 0.f, s3 = 0.f;
        #pragma unroll
        for (int k4 = 0; k4 < KPP/4; k4++) {
            float4 p = prow[k4];
            s0 += fabsf(p.x - dk[k4*4+0]);
            s1 += fabsf(p.y - dk[k4*4+1]);
            s2 += fabsf(p.z - dk[k4*4+2]);
            s3 += fabsf(p.w - dk[k4*4+3]);
        }
        float s = (s0 + s1) + (s2 + s3);

        // GIoU
        float pmn[3], pmx[3];
        #pragma unroll
        for (int d = 0; d < 3; d++) {
            float cc = buf[RBLK*KPP + r*6 + d];
            float ss = buf[RBLK*KPP + r*6 + 3 + d];
            pmn[d] = cc - 0.5f*ss; pmx[d] = cc + 0.5f*ss;
        }
        float vol1 = (pmx[0]-pmn[0])*(pmx[1]-pmn[1])*(pmx[2]-pmn[2]);
        float inter = 1.f, evol = 1.f;
        #pragma unroll
        for (int d = 0; d < 3; d++) {
            inter *= fmaxf(fminf(pmx[d], tmx[d]) - fmaxf(pmn[d], tmn[d]), 0.f);
            evol  *= fmaxf(fmaxf(pmx[d], tmx[d]) - fminf(pmn[d], tmn[d]), 0.f);
        }
        float uni  = vol1 + tvol - inter;
        float cost = s - (inter/uni - (evol - uni)/evol);

        int rr = r0 + r;
        C[(size_t)rr*NCOL + c] = cost;
        if (rr / NQ == bc)                        // diagonal block -> LAP staging
            g_lap[(size_t)(bc*NT + tloc)*NQ + (rr - bc*NQ)] = cost;
    }
}

// ---------------------------------------------------------
// Kernel 2: LAP with JV greedy initialization.
//  1) stage 50x300 block into smem (256 threads)
//  2) 8 warps compute per-row min+argmin
//  3) warp 0: greedy assign conflict-free rows, Dijkstra only for the rest
// ---------------------------------------------------------
__global__ void __launch_bounds__(256) lap_kernel(float* __restrict__ out) {
    extern __shared__ float smc[];         // [NT*NQ] cost block
    const int b   = blockIdx.x;
    const int tid = threadIdx.x;
    const int lane = tid & 31;
    const int wid  = tid >> 5;
    const float INF = 3.0e38f;

    __shared__ float u[NT];
    __shared__ float rmin[NT];
    __shared__ int   ramin[NT];
    __shared__ int   path[NQ];
    __shared__ int   row4col[NQ];
    __shared__ int   col4row[NT];
    __shared__ int   selj[NQ + 2];
    __shared__ float selv[NQ + 2];

    // stage cost block
    {
        const float4* src = (const float4*)&g_lap[(size_t)b*NT*NQ];
        float4* dst = (float4*)smc;
        #pragma unroll 4
        for (int i = tid; i < NT*NQ/4; i += 256) dst[i] = src[i];
    }
    __syncthreads();

    // per-row min + argmin (8 warps over 50 rows)
    for (int row = wid; row < NT; row += 8) {
        const float* rp = smc + row*NQ;
        float bv = INF; int bi = NQ;
        for (int j = lane; j < NQ; j += 32) {
            float v = rp[j];
            if (v < bv) { bv = v; bi = j; }
        }
        int fi = warp_argmin(bv, bi);
        if (lane == 0) { rmin[row] = bv; ramin[row] = fi; }
    }
    __syncthreads();
    if (tid >= 32) return;                 // warp 0 solves alone

    float shortest[NK];
    float vloc[NK];

    for (int j = lane; j < NQ; j += 32) row4col[j] = -1;
    for (int t = lane; t < NT; t += 32) { u[t] = rmin[t]; col4row[t] = -1; }
    #pragma unroll
    for (int k = 0; k < NK; k++) vloc[k] = 0.f;
    __syncwarp();

    // greedy conflict-free assignment (serial, tiny)
    if (lane == 0) {
        #pragma unroll 1
        for (int i = 0; i < NT; i++) {
            int j = ramin[i];
            if (row4col[j] == -1) { row4col[j] = i; col4row[i] = j; }
        }
    }
    __syncwarp();

    for (int curRow = 0; curRow < NT; curRow++) {
        if (col4row[curRow] != -1) continue;   // already assigned greedily

        #pragma unroll
        for (int k = 0; k < NK; k++) shortest[k] = INF;
        unsigned sc = 0;
        int   i  = curRow;
        float mv = 0.f;
        int   nsteps = 0;
        int   sink = -1;

        while (true) {
            const float base = mv - u[i];
            const float* lrow = smc + i*NQ;

            float bv = INF; int bi = NQ;
            #pragma unroll
            for (int k = 0; k < NK; k++) {
                int j = k*32 + lane;
                if (j < NQ && !((sc >> k) & 1u)) {
                    float rr = base + lrow[j] - vloc[k];
                    if (rr < shortest[k]) { shortest[k] = rr; path[j] = i; }
                    if (shortest[k] < bv) { bv = shortest[k]; bi = j; }
                }
            }

            int fi = warp_argmin(bv, bi);
            mv = bv;

            if (lane == (fi & 31)) sc |= 1u << (fi >> 5);
            if (lane == 0) { selj[nsteps] = fi; selv[nsteps] = mv; }
            nsteps++;

            int r4 = row4col[fi];
            if (r4 == -1) { sink = fi; break; }
            i = r4;
        }

        __syncwarp();

        // dual updates (pre-augmentation row4col)
        if (lane == 0) u[curRow] += mv;
        for (int s = lane; s < nsteps - 1; s += 32) {
            int i2 = row4col[selj[s]];
            u[i2] += mv - selv[s];
        }
        for (int s = 0; s < nsteps; s++) {
            int j = selj[s];
            if ((j & 31) == lane) vloc[j >> 5] -= mv - selv[s];
        }
        __syncwarp();

        // augment
        if (lane == 0) {
            int j = sink;
            while (true) {
                int i2 = path[j];
                row4col[j] = i2;
                int nj = col4row[i2];
                col4row[i2] = j;
                j = nj;
                if (i2 == curRow) break;
            }
        }
        __syncwarp();
    }

    // emit indices sorted by query (rank counting)
    for (int t = lane; t < NT; t += 32) {
        int q = col4row[t];
        int rank = 0;
        #pragma unroll
        for (int t2 = 0; t2 < NT; t2++) rank += (col4row[t2] < q) ? 1 : 0;
        size_t base = (size_t)NROW * NCOL + (size_t)b * 2 * NT;
        out[base + rank]      = (float)q;
        out[base + NT + rank] = (float)t;
    }
}

// ---------------------------------------------------------
extern "C" void kernel_launch(void* const* d_in, const int* in_sizes, int n_in,
                              void* d_out, int out_size) {
    const float* pred_kp   = (const float*)d_in[0];  // (16,300,51)
    const float* pred_box  = (const float*)d_in[1];  // (16,300,6)
    const float* tgt_box   = (const float*)d_in[2];  // (16,50,6)
    const float* tgt_kp    = (const float*)d_in[3];  // (16,50,51)
    float* out = (float*)d_out;

    const int lap_smem = NT*NQ*(int)sizeof(float);   // 60000 B
    cudaFuncSetAttribute(lap_kernel, cudaFuncAttributeMaxDynamicSharedMemorySize, lap_smem);

    dim3 cg(NCOL/CBLK, NROW/RBLK);     // (5, 50)
    cost_kernel<<<cg, CBLK>>>(pred_kp, pred_box, tgt_kp, tgt_box, out);

    lap_kernel<<<BS, 256, lap_smem>>>(out);
}

// round 5
// speedup vs baseline: 1.6328x; 1.1130x over previous
#include <cuda_runtime.h>
#include <cuda_bf16.h>

#define BS 16
#define NQ 300
#define NT 50
#define KP3 51          // 17 keypoints * 3
#define KPP 52          // padded (float4/ull2-friendly)
#define NCOL (BS*NT)    // 800
#define NROW (BS*NQ)    // 4800
#define NK 10           // columns per lane in LAP (10*32 >= 300)
#define CBLK 160        // cols per cost block
#define RBLK 96         // rows per cost block

typedef unsigned long long ull;

__device__ float g_lap[BS*NT*NQ];      // per-batch transposed cost [b][t][q]

#define ADD_F32X2(out, a, b) \
    asm("add.rn.f32x2 %0, %1, %2;" : "=l"(out) : "l"(a), "l"(b))

// monotonic float<->uint order-preserving map (for redux.min)
__device__ __forceinline__ unsigned fmap(float f) {
    unsigned u = __float_as_uint(f);
    return (u & 0x80000000u) ? ~u : (u | 0x80000000u);
}
__device__ __forceinline__ float finv(unsigned u) {
    return __uint_as_float((u & 0x80000000u) ? (u & 0x7FFFFFFFu) : ~u);
}

// warp argmin (any tie-break): 1 redux + ballot + shfl
__device__ __forceinline__ int warp_argmin(float& bv, int bi) {
    unsigned bu  = fmap(bv);
    unsigned mvu = __reduce_min_sync(0xffffffffu, bu);
    unsigned bal = __ballot_sync(0xffffffffu, bu == mvu);
    int src = __ffs(bal) - 1;
    bv = finv(mvu);
    return __shfl_sync(0xffffffffu, bi, src);
}

// ---------------------------------------------------------
// Kernel 1: cost matrix, fused target preprocessing.
// block = 160 threads (one column each), 96 rows per block. grid (5,50).
// ---------------------------------------------------------
__global__ void __launch_bounds__(CBLK) cost_kernel(const float* __restrict__ pkp,
                                                    const float* __restrict__ pbox,
                                                    const float* __restrict__ tkp,
                                                    const float* __restrict__ tbox,
                                                    float* __restrict__ C) {
    __shared__ __align__(16) float buf[CBLK*(KP3+6)];   // A: tgt slice; B: pred slice
    const int tid = threadIdx.x;
    const int c0  = blockIdx.x * CBLK;
    const int r0  = blockIdx.y * RBLK;
    const int c   = c0 + tid;

    // ---- phase A: coalesced load of target slice, then to registers ----
    for (int i = tid; i < CBLK*KP3; i += CBLK) buf[i] = tkp[c0*KP3 + i];
    for (int i = tid; i < CBLK*6;  i += CBLK) buf[CBLK*KP3 + i] = tbox[c0*6 + i];
    __syncthreads();

    ull  ndk[KPP/2];           // packed (-dk) pairs
    float tmn[3], tmx[3], tvol;
    {
        float sz[3];
        #pragma unroll
        for (int d = 0; d < 3; d++) {
            float ctr = buf[CBLK*KP3 + tid*6 + d];
            sz[d]     = buf[CBLK*KP3 + tid*6 + 3 + d];
            tmn[d] = ctr - 0.5f*sz[d];
            tmx[d] = ctr + 0.5f*sz[d];
        }
        tvol = (tmx[0]-tmn[0])*(tmx[1]-tmn[1])*(tmx[2]-tmn[2]);
        float dk[KPP];
        #pragma unroll
        for (int k = 0; k < KP3; k++) {
            int d = k - (k/3)*3;
            dk[k] = (buf[tid*KP3 + k] - tmn[d]) / sz[d];
        }
        dk[KP3] = 0.f;
        #pragma unroll
        for (int k2 = 0; k2 < KPP/2; k2++) {
            float lo = -dk[2*k2], hi = -dk[2*k2+1];
            asm("mov.b64 %0, {%1, %2};" : "=l"(ndk[k2]) : "f"(lo), "f"(hi));
        }
    }
    __syncthreads();

    // ---- phase B: pred rows padded to 52 floats + boxes ----
    for (int i = tid; i < RBLK*KPP; i += CBLK) {
        int r = i / KPP, k = i - r*KPP;
        buf[i] = (k < KP3) ? pkp[(size_t)(r0+r)*KP3 + k] : 0.f;
    }
    for (int i = tid; i < RBLK*6;  i += CBLK) buf[RBLK*KPP + i] = pbox[(size_t)r0*6 + i];
    __syncthreads();

    const int bc   = c / NT;
    const int tloc = c - bc*NT;
    const ull AMASK = 0x7FFFFFFF7FFFFFFFULL;

    for (int r = 0; r < RBLK; r++) {
        // keypoint L1: 13 x LDS.128 + f32x2 sub/acc on fma pipe, abs on alu pipe
        const ulonglong2* prow = (const ulonglong2*)&buf[r*KPP];
        ull sA = 0, sB = 0;
        #pragma unroll
        for (int k4 = 0; k4 < KPP/4; k4++) {
            ulonglong2 p = prow[k4];
            ull d0; ADD_F32X2(d0, p.x, ndk[2*k4]);
            d0 &= AMASK;
            ADD_F32X2(sA, sA, d0);
            ull d1; ADD_F32X2(d1, p.y, ndk[2*k4+1]);
            d1 &= AMASK;
            ADD_F32X2(sB, sB, d1);
        }
        ull st; ADD_F32X2(st, sA, sB);
        float slo, shi;
        asm("mov.b64 {%0, %1}, %2;" : "=f"(slo), "=f"(shi) : "l"(st));
        float s = slo + shi;

        // GIoU
        float pmn[3], pmx[3];
        #pragma unroll
        for (int d = 0; d < 3; d++) {
            float cc = buf[RBLK*KPP + r*6 + d];
            float ss = buf[RBLK*KPP + r*6 + 3 + d];
            pmn[d] = cc - 0.5f*ss; pmx[d] = cc + 0.5f*ss;
        }
        float vol1 = (pmx[0]-pmn[0])*(pmx[1]-pmn[1])*(pmx[2]-pmn[2]);
        float inter = 1.f, evol = 1.f;
        #pragma unroll
        for (int d = 0; d < 3; d++) {
            inter *= fmaxf(fminf(pmx[d], tmx[d]) - fmaxf(pmn[d], tmn[d]), 0.f);
            evol  *= fmaxf(fmaxf(pmx[d], tmx[d]) - fminf(pmn[d], tmn[d]), 0.f);
        }
        float uni  = vol1 + tvol - inter;
        float cost = s - (inter/uni - (evol - uni)/evol);

        int rr = r0 + r;
        C[(size_t)rr*NCOL + c] = cost;
        if (rr / NQ == bc)
            g_lap[(size_t)(bc*NT + tloc)*NQ + (rr - bc*NQ)] = cost;
    }
}

// ---------------------------------------------------------
// Kernel 2: LAP = greedy row-min init + JV augmenting row reduction
//           + shortest augmenting path for the remainder.
// ---------------------------------------------------------
__global__ void __launch_bounds__(256) lap_kernel(float* __restrict__ out) {
    extern __shared__ float smc[];         // [NT*NQ] cost block
    const int b   = blockIdx.x;
    const int tid = threadIdx.x;
    const int lane = tid & 31;
    const int wid  = tid >> 5;
    const float INF = 3.0e38f;

    __shared__ float u[NT];
    __shared__ float rmin[NT];
    __shared__ int   ramin[NT];
    __shared__ int   path[NQ];
    __shared__ int   row4col[NQ];
    __shared__ int   col4row[NT];
    __shared__ int   selj[NQ + 2];
    __shared__ float selv[NQ + 2];
    __shared__ int   freelist[NT];

    // stage cost block
    {
        const float4* src = (const float4*)&g_lap[(size_t)b*NT*NQ];
        float4* dst = (float4*)smc;
        #pragma unroll 4
        for (int i = tid; i < NT*NQ/4; i += 256) dst[i] = src[i];
    }
    __syncthreads();

    // per-row min + argmin (8 warps over 50 rows)
    for (int row = wid; row < NT; row += 8) {
        const float* rp = smc + row*NQ;
        float bv = INF; int bi = NQ;
        for (int j = lane; j < NQ; j += 32) {
            float v = rp[j];
            if (v < bv) { bv = v; bi = j; }
        }
        int fi = warp_argmin(bv, bi);
        if (lane == 0) { rmin[row] = bv; ramin[row] = fi; }
    }
    __syncthreads();
    if (tid >= 32) return;                 // warp 0 solves alone

    float shortest[NK];
    float vloc[NK];

    for (int j = lane; j < NQ; j += 32) row4col[j] = -1;
    for (int t = lane; t < NT; t += 32) { u[t] = rmin[t]; col4row[t] = -1; }
    #pragma unroll
    for (int k = 0; k < NK; k++) vloc[k] = 0.f;
    __syncwarp();

    // greedy conflict-free assignment
    if (lane == 0) {
        #pragma unroll 1
        for (int i = 0; i < NT; i++) {
            int j = ramin[i];
            if (row4col[j] == -1) { row4col[j] = i; col4row[i] = j; }
        }
    }
    __syncwarp();

    // collect unassigned rows
    int nfree = 0;
    #pragma unroll
    for (int base = 0; base < NT; base += 32) {
        int t = base + lane;
        bool fr = (t < NT) && (col4row[t] == -1);
        unsigned m = __ballot_sync(0xffffffffu, fr);
        int pos = nfree + __popc(m & ((1u << lane) - 1u));
        if (fr) freelist[pos] = t;
        nfree += __popc(m);
    }
    __syncwarp();

    // ---- JV augmenting row reduction (displacement chains) ----
    {
        int scans = 0;
        const int CAP = 8 * NT;
        for (int idx = 0; idx < nfree && scans < CAP; idx++) {
            int i = freelist[idx];
            while (i != -1 && scans < CAP) {
                scans++;
                // scan row i: min (u1 at j1) and second-min (u2) of c[i,j]-v[j]
                const float* lrow = smc + i*NQ;
                float l1 = INF, l2 = INF; int b1 = NQ;
                #pragma unroll
                for (int k = 0; k < NK; k++) {
                    int j = k*32 + lane;
                    if (j < NQ) {
                        float w = lrow[j] - vloc[k];
                        if (w < l1) { l2 = l1; l1 = w; b1 = j; }
                        else if (w < l2) l2 = w;
                    }
                }
                unsigned m1 = __reduce_min_sync(0xffffffffu, fmap(l1));
                unsigned bal = __ballot_sync(0xffffffffu, fmap(l1) == m1);
                int win = __ffs(bal) - 1;
                int j1  = __shfl_sync(0xffffffffu, b1, win);
                float u1 = finv(m1);
                float cand = (lane == win) ? l2 : l1;
                float u2 = finv(__reduce_min_sync(0xffffffffu, fmap(cand)));

                int i1 = row4col[j1];        // pre-assign owner (uniform)
                if (!(u1 < u2) && i1 != -1) break;   // degenerate tie -> Dijkstra
                if (lane == (j1 & 31) && u1 < u2) vloc[j1 >> 5] -= (u2 - u1);
                if (lane == 0) {
                    u[i] = u2;
                    row4col[j1] = i;
                    col4row[i]  = j1;
                    if (i1 != -1) col4row[i1] = -1;
                }
                __syncwarp();
                i = i1;                      // continue chain with displaced row
            }
        }
    }
    __syncwarp();

    // ---- shortest augmenting path for whatever remains ----
    for (int curRow = 0; curRow < NT; curRow++) {
        if (col4row[curRow] != -1) continue;

        #pragma unroll
        for (int k = 0; k < NK; k++) shortest[k] = INF;
        unsigned sc = 0;
        int   i  = curRow;
        float mv = 0.f;
        int   nsteps = 0;
        int   sink = -1;

        while (true) {
            const float base = mv - u[i];
            const float* lrow = smc + i*NQ;

            float bv = INF; int bi = NQ;
            #pragma unroll
            for (int k = 0; k < NK; k++) {
                int j = k*32 + lane;
                if (j < NQ && !((sc >> k) & 1u)) {
                    float rr = base + lrow[j] - vloc[k];
                    if (rr < shortest[k]) { shortest[k] = rr; path[j] = i; }
                    if (shortest[k] < bv) { bv = shortest[k]; bi = j; }
                }
            }

            int fi = warp_argmin(bv, bi);
            mv = bv;

            if (lane == (fi & 31)) sc |= 1u << (fi >> 5);
            if (lane == 0) { selj[nsteps] = fi; selv[nsteps] = mv; }
            nsteps++;

            int r4 = row4col[fi];
            if (r4 == -1) { sink = fi; break; }
            i = r4;
        }

        __syncwarp();

        // dual updates (pre-augmentation row4col)
        if (lane == 0) u[curRow] += mv;
        for (int s = lane; s < nsteps - 1; s += 32) {
            int i2 = row4col[selj[s]];
            u[i2] += mv - selv[s];
        }
        for (int s = 0; s < nsteps; s++) {
            int j = selj[s];
            if ((j & 31) == lane) vloc[j >> 5] -= mv - selv[s];
        }
        __syncwarp();

        // augment
        if (lane == 0) {
            int j = sink;
            while (true) {
                int i2 = path[j];
                row4col[j] = i2;
                int nj = col4row[i2];
                col4row[i2] = j;
                j = nj;
                if (i2 == curRow) break;
            }
        }
        __syncwarp();
    }

    // emit indices sorted by query (rank counting)
    for (int t = lane; t < NT; t += 32) {
        int q = col4row[t];
        int rank = 0;
        #pragma unroll
        for (int t2 = 0; t2 < NT; t2++) rank += (col4row[t2] < q) ? 1 : 0;
        size_t base = (size_t)NROW * NCOL + (size_t)b * 2 * NT;
        out[base + rank]      = (float)q;
        out[base + NT + rank] = (float)t;
    }
}

// ---------------------------------------------------------
extern "C" void kernel_launch(void* const* d_in, const int* in_sizes, int n_in,
                              void* d_out, int out_size) {
    const float* pred_kp   = (const float*)d_in[0];  // (16,300,51)
    const float* pred_box  = (const float*)d_in[1];  // (16,300,6)
    const float* tgt_box   = (const float*)d_in[2];  // (16,50,6)
    const float* tgt_kp    = (const float*)d_in[3];  // (16,50,51)
    float* out = (float*)d_out;

    const int lap_smem = NT*NQ*(int)sizeof(float);   // 60000 B
    cudaFuncSetAttribute(lap_kernel, cudaFuncAttributeMaxDynamicSharedMemorySize, lap_smem);

    dim3 cg(NCOL/CBLK, NROW/RBLK);     // (5, 50)
    cost_kernel<<<cg, CBLK>>>(pred_kp, pred_box, tgt_kp, tgt_box, out);

    lap_kernel<<<BS, 256, lap_smem>>>(out);
}

// round 6
// speedup vs baseline: 1.8721x; 1.1466x over previous
#include <cuda_runtime.h>
#include <cuda_bf16.h>

#define BS 16
#define NQ 300
#define NT 50
#define KP3 51          // 17 keypoints * 3
#define KPP 52          // padded (float4/ull2-friendly)
#define NCOL (BS*NT)    // 800
#define NROW (BS*NQ)    // 4800
#define NK 10           // columns per lane in LAP (10*32 >= 300)
#define CBLK 160        // cols per cost block
#define RBLK 32         // rows per cost block
#define GBX  (NCOL/CBLK)   // 5
#define GBY  (NROW/RBLK)   // 150

typedef unsigned long long ull;

#define ADD_F32X2(out, a, b) \
    asm("add.rn.f32x2 %0, %1, %2;" : "=l"(out) : "l"(a), "l"(b))

__device__ __forceinline__ unsigned fmap(float f) {
    unsigned u = __float_as_uint(f);
    return (u & 0x80000000u) ? ~u : (u | 0x80000000u);
}
__device__ __forceinline__ float finv(unsigned u) {
    return __uint_as_float((u & 0x80000000u) ? (u & 0x7FFFFFFFu) : ~u);
}
__device__ __forceinline__ int warp_argmin(float& bv, int bi) {
    unsigned bu  = fmap(bv);
    unsigned mvu = __reduce_min_sync(0xffffffffu, bu);
    unsigned bal = __ballot_sync(0xffffffffu, bu == mvu);
    int src = __ffs(bal) - 1;
    bv = finv(mvu);
    return __shfl_sync(0xffffffffu, bi, src);
}

// ---------------------------------------------------------
// Fused kernel. blocks [0,16): diag-cost + LAP.  blocks [16,766): C matrix.
// ---------------------------------------------------------
__global__ void __launch_bounds__(256) fused_kernel(const float* __restrict__ pkp,
                                                    const float* __restrict__ pbox,
                                                    const float* __restrict__ tkp,
                                                    const float* __restrict__ tbox,
                                                    float* __restrict__ out) {
    extern __shared__ __align__(16) float dsm[];   // cost: buf | lap: smc[NT*NQ]
    const int tid = threadIdx.x;

    if (blockIdx.x >= BS) {
        // ================== COST-MATRIX PATH ==================
        float* buf = dsm;
        const int cb = blockIdx.x - BS;
        const int c0 = (cb % GBX) * CBLK;
        const int r0 = (cb / GBX) * RBLK;
        const int c  = c0 + (tid < CBLK ? tid : 0);   // threads >=CBLK only help loads

        // phase A: target slice -> registers
        for (int i = tid; i < CBLK*KP3; i += 256) buf[i] = tkp[c0*KP3 + i];
        for (int i = tid; i < CBLK*6;  i += 256) buf[CBLK*KP3 + i] = tbox[c0*6 + i];
        __syncthreads();

        ull  ndk[KPP/2];
        float tmn[3], tmx[3], tvol = 0.f;
        {
            float sz[3];
            #pragma unroll
            for (int d = 0; d < 3; d++) {
                float ctr = buf[CBLK*KP3 + (c-c0)*6 + d];
                sz[d]     = buf[CBLK*KP3 + (c-c0)*6 + 3 + d];
                tmn[d] = ctr - 0.5f*sz[d];
                tmx[d] = ctr + 0.5f*sz[d];
            }
            tvol = (tmx[0]-tmn[0])*(tmx[1]-tmn[1])*(tmx[2]-tmn[2]);
            float dk[KPP];
            #pragma unroll
            for (int k = 0; k < KP3; k++) {
                int d = k - (k/3)*3;
                dk[k] = (buf[(c-c0)*KP3 + k] - tmn[d]) / sz[d];
            }
            dk[KP3] = 0.f;
            #pragma unroll
            for (int k2 = 0; k2 < KPP/2; k2++) {
                float lo = -dk[2*k2], hi = -dk[2*k2+1];
                asm("mov.b64 %0, {%1, %2};" : "=l"(ndk[k2]) : "f"(lo), "f"(hi));
            }
        }
        __syncthreads();

        // phase B: pred rows padded to 52 + boxes
        for (int i = tid; i < RBLK*KPP; i += 256) {
            int r = i / KPP, k = i - r*KPP;
            buf[i] = (k < KP3) ? pkp[(size_t)(r0+r)*KP3 + k] : 0.f;
        }
        for (int i = tid; i < RBLK*6; i += 256) buf[RBLK*KPP + i] = pbox[(size_t)r0*6 + i];
        __syncthreads();
        if (tid >= CBLK) return;

        const ull AMASK = 0x7FFFFFFF7FFFFFFFULL;
        #pragma unroll 2
        for (int r = 0; r < RBLK; r++) {
            const ulonglong2* prow = (const ulonglong2*)&buf[r*KPP];
            ull sA = 0, sB = 0;
            #pragma unroll
            for (int k4 = 0; k4 < KPP/4; k4++) {
                ulonglong2 p = prow[k4];
                ull d0; ADD_F32X2(d0, p.x, ndk[2*k4]);
                d0 &= AMASK;
                ADD_F32X2(sA, sA, d0);
                ull d1; ADD_F32X2(d1, p.y, ndk[2*k4+1]);
                d1 &= AMASK;
                ADD_F32X2(sB, sB, d1);
            }
            ull st; ADD_F32X2(st, sA, sB);
            float slo, shi;
            asm("mov.b64 {%0, %1}, %2;" : "=f"(slo), "=f"(shi) : "l"(st));
            float s = slo + shi;

            float pmn[3], pmx[3];
            #pragma unroll
            for (int d = 0; d < 3; d++) {
                float cc = buf[RBLK*KPP + r*6 + d];
                float ss = buf[RBLK*KPP + r*6 + 3 + d];
                pmn[d] = cc - 0.5f*ss; pmx[d] = cc + 0.5f*ss;
            }
            float vol1 = (pmx[0]-pmn[0])*(pmx[1]-pmn[1])*(pmx[2]-pmn[2]);
            float inter = 1.f, evol = 1.f;
            #pragma unroll
            for (int d = 0; d < 3; d++) {
                inter *= fmaxf(fminf(pmx[d], tmx[d]) - fmaxf(pmn[d], tmn[d]), 0.f);
                evol  *= fmaxf(fmaxf(pmx[d], tmx[d]) - fminf(pmn[d], tmn[d]), 0.f);
            }
            float uni = vol1 + tvol - inter;
            out[(size_t)(r0+r)*NCOL + c] = s - (inter/uni - (evol - uni)/evol);
        }
        return;
    }

    // ================== LAP PATH (blocks 0..15) ==================
    float* smc = dsm;                   // [NT*NQ] diag cost block
    const int b    = blockIdx.x;
    const int lane = tid & 31;
    const int wid  = tid >> 5;
    const float INF = 3.0e38f;

    __shared__ __align__(16) float sdk[NT][KPP];   // per-target normalized kp
    __shared__ float stmn[NT][3], stmx[NT][3], stvol[NT];
    __shared__ float u[NT];
    __shared__ float rmin[NT];
    __shared__ int   ramin[NT];
    __shared__ int   path[NQ];
    __shared__ int   row4col[NQ];
    __shared__ int   col4row[NT];
    __shared__ int   selj[NQ + 2];
    __shared__ float selv[NQ + 2];
    __shared__ int   freelist[NT];

    // per-target preprocessing
    if (tid < NT) {
        int g = b*NT + tid;
        float sz[3];
        #pragma unroll
        for (int d = 0; d < 3; d++) {
            float ctr = tbox[g*6 + d];
            sz[d]     = tbox[g*6 + 3 + d];
            stmn[tid][d] = ctr - 0.5f*sz[d];
            stmx[tid][d] = ctr + 0.5f*sz[d];
        }
        stvol[tid] = sz[0]*sz[1]*sz[2];
        #pragma unroll
        for (int k = 0; k < KP3; k++) {
            int d = k - (k/3)*3;
            sdk[tid][k] = (tkp[(size_t)g*KP3 + k] - stmn[tid][d]) / sz[d];
        }
        sdk[tid][KP3] = 0.f;
    }
    __syncthreads();

    // diag cost block: thread handles queries q, q+256
    for (int q = tid; q < NQ; q += 256) {
        float4 pk4[KPP/4];
        {
            float tmpk[KPP];
            const float* pr = pkp + (size_t)(b*NQ + q)*KP3;
            #pragma unroll
            for (int k = 0; k < KP3; k++) tmpk[k] = pr[k];
            tmpk[KP3] = 0.f;
            #pragma unroll
            for (int k4 = 0; k4 < KPP/4; k4++)
                pk4[k4] = make_float4(tmpk[4*k4], tmpk[4*k4+1], tmpk[4*k4+2], tmpk[4*k4+3]);
        }
        float pmn[3], pmx[3];
        #pragma unroll
        for (int d = 0; d < 3; d++) {
            float cc = pbox[(size_t)(b*NQ + q)*6 + d];
            float ss = pbox[(size_t)(b*NQ + q)*6 + 3 + d];
            pmn[d] = cc - 0.5f*ss; pmx[d] = cc + 0.5f*ss;
        }
        float vol1 = (pmx[0]-pmn[0])*(pmx[1]-pmn[1])*(pmx[2]-pmn[2]);

        for (int t = 0; t < NT; t++) {
            const float4* srow = (const float4*)sdk[t];
            float s0 = 0.f, s1 = 0.f, s2 = 0.f, s3 = 0.f;
            #pragma unroll
            for (int k4 = 0; k4 < KPP/4; k4++) {
                float4 d4 = srow[k4];
                s0 += fabsf(pk4[k4].x - d4.x);
                s1 += fabsf(pk4[k4].y - d4.y);
                s2 += fabsf(pk4[k4].z - d4.z);
                s3 += fabsf(pk4[k4].w - d4.w);
            }
            float s = (s0 + s1) + (s2 + s3);
            float inter = 1.f, evol = 1.f;
            #pragma unroll
            for (int d = 0; d < 3; d++) {
                float tn = stmn[t][d], tx = stmx[t][d];
                inter *= fmaxf(fminf(pmx[d], tx) - fmaxf(pmn[d], tn), 0.f);
                evol  *= fmaxf(fmaxf(pmx[d], tx) - fminf(pmn[d], tn), 0.f);
            }
            float uni = vol1 + stvol[t] - inter;
            smc[t*NQ + q] = s - (inter/uni - (evol - uni)/evol);
        }
    }
    __syncthreads();

    // per-row min + argmin (8 warps over 50 rows)
    for (int row = wid; row < NT; row += 8) {
        const float* rp = smc + row*NQ;
        float bv = INF; int bi = NQ;
        for (int j = lane; j < NQ; j += 32) {
            float v = rp[j];
            if (v < bv) { bv = v; bi = j; }
        }
        int fi = warp_argmin(bv, bi);
        if (lane == 0) { rmin[row] = bv; ramin[row] = fi; }
    }
    __syncthreads();
    if (tid >= 32) return;                 // warp 0 solves alone

    float shortest[NK];
    float vloc[NK];

    for (int j = lane; j < NQ; j += 32) row4col[j] = -1;
    for (int t = lane; t < NT; t += 32) { u[t] = rmin[t]; col4row[t] = -1; }
    #pragma unroll
    for (int k = 0; k < NK; k++) vloc[k] = 0.f;
    __syncwarp();

    // greedy conflict-free assignment
    if (lane == 0) {
        #pragma unroll 1
        for (int i = 0; i < NT; i++) {
            int j = ramin[i];
            if (row4col[j] == -1) { row4col[j] = i; col4row[i] = j; }
        }
    }
    __syncwarp();

    // collect unassigned rows
    int nfree = 0;
    #pragma unroll
    for (int base = 0; base < NT; base += 32) {
        int t = base + lane;
        bool fr = (t < NT) && (col4row[t] == -1);
        unsigned m = __ballot_sync(0xffffffffu, fr);
        int pos = nfree + __popc(m & ((1u << lane) - 1u));
        if (fr) freelist[pos] = t;
        nfree += __popc(m);
    }
    __syncwarp();

    // JV augmenting row reduction (displacement chains)
    {
        int scans = 0;
        const int CAP = 8 * NT;
        for (int idx = 0; idx < nfree && scans < CAP; idx++) {
            int i = freelist[idx];
            while (i != -1 && scans < CAP) {
                scans++;
                const float* lrow = smc + i*NQ;
                float l1 = INF, l2 = INF; int b1 = NQ;
                #pragma unroll
                for (int k = 0; k < NK; k++) {
                    int j = k*32 + lane;
                    if (j < NQ) {
                        float w = lrow[j] - vloc[k];
                        if (w < l1) { l2 = l1; l1 = w; b1 = j; }
                        else if (w < l2) l2 = w;
                    }
                }
                unsigned m1 = __reduce_min_sync(0xffffffffu, fmap(l1));
                unsigned bal = __ballot_sync(0xffffffffu, fmap(l1) == m1);
                int win = __ffs(bal) - 1;
                int j1  = __shfl_sync(0xffffffffu, b1, win);
                float u1 = finv(m1);
                float cand = (lane == win) ? l2 : l1;
                float u2 = finv(__reduce_min_sync(0xffffffffu, fmap(cand)));

                int i1 = row4col[j1];
                if (!(u1 < u2) && i1 != -1) break;   // degenerate tie -> Dijkstra
                if (lane == (j1 & 31) && u1 < u2) vloc[j1 >> 5] -= (u2 - u1);
                if (lane == 0) {
                    u[i] = u2;
                    row4col[j1] = i;
                    col4row[i]  = j1;
                    if (i1 != -1) col4row[i1] = -1;
                }
                __syncwarp();
                i = i1;
            }
        }
    }
    __syncwarp();

    // shortest augmenting path for whatever remains
    for (int curRow = 0; curRow < NT; curRow++) {
        if (col4row[curRow] != -1) continue;

        #pragma unroll
        for (int k = 0; k < NK; k++) shortest[k] = INF;
        unsigned sc = 0;
        int   i  = curRow;
        float mv = 0.f;
        int   nsteps = 0;
        int   sink = -1;

        while (true) {
            const float base = mv - u[i];
            const float* lrow = smc + i*NQ;

            float bv = INF; int bi = NQ;
            #pragma unroll
            for (int k = 0; k < NK; k++) {
                int j = k*32 + lane;
                if (j < NQ && !((sc >> k) & 1u)) {
                    float rr = base + lrow[j] - vloc[k];
                    if (rr < shortest[k]) { shortest[k] = rr; path[j] = i; }
                    if (shortest[k] < bv) { bv = shortest[k]; bi = j; }
                }
            }

            int fi = warp_argmin(bv, bi);
            mv = bv;

            if (lane == (fi & 31)) sc |= 1u << (fi >> 5);
            if (lane == 0) { selj[nsteps] = fi; selv[nsteps] = mv; }
            nsteps++;

            int r4 = row4col[fi];
            if (r4 == -1) { sink = fi; break; }
            i = r4;
        }

        __syncwarp();

        if (lane == 0) u[curRow] += mv;
        for (int s = lane; s < nsteps - 1; s += 32) {
            int i2 = row4col[selj[s]];
            u[i2] += mv - selv[s];
        }
        for (int s = 0; s < nsteps; s++) {
            int j = selj[s];
            if ((j & 31) == lane) vloc[j >> 5] -= mv - selv[s];
        }
        __syncwarp();

        if (lane == 0) {
            int j = sink;
            while (true) {
                int i2 = path[j];
                row4col[j] = i2;
                int nj = col4row[i2];
                col4row[i2] = j;
                j = nj;
                if (i2 == curRow) break;
            }
        }
        __syncwarp();
    }

    // emit indices sorted by query (rank counting)
    for (int t = lane; t < NT; t += 32) {
        int q = col4row[t];
        int rank = 0;
        #pragma unroll
        for (int t2 = 0; t2 < NT; t2++) rank += (col4row[t2] < q) ? 1 : 0;
        size_t base = (size_t)NROW * NCOL + (size_t)b * 2 * NT;
        out[base + rank]      = (float)q;
        out[base + NT + rank] = (float)t;
    }
}

// ---------------------------------------------------------
extern "C" void kernel_launch(void* const* d_in, const int* in_sizes, int n_in,
                              void* d_out, int out_size) {
    const float* pred_kp   = (const float*)d_in[0];  // (16,300,51)
    const float* pred_box  = (const float*)d_in[1];  // (16,300,6)
    const float* tgt_box   = (const float*)d_in[2];  // (16,50,6)
    const float* tgt_kp    = (const float*)d_in[3];  // (16,50,51)
    float* out = (float*)d_out;

    const int dyn_smem = NT*NQ*(int)sizeof(float);   // 60000 B (>= cost buf 36.5KB)
    cudaFuncSetAttribute(fused_kernel, cudaFuncAttributeMaxDynamicSharedMemorySize, dyn_smem);

    fused_kernel<<<BS + GBX*GBY, 256, dyn_smem>>>(pred_kp, pred_box, tgt_kp, tgt_box, out);
}